// round 1
// baseline (speedup 1.0000x reference)
#include <cuda_runtime.h>
#include <cuda_bf16.h>
#include <math.h>

#define NROWS 8000
#define D 256
#define P 128
#define CAP 192   // max nnz per row; binomial(8000,0.008) max ~95, huge margin

// ---------------- device scratch (no allocations allowed) ----------------
__device__ int   g_cols[NROWS * CAP];   // nonzero column indices per row
__device__ int   g_deg [NROWS];         // nnz per row
__device__ float g_dinv[NROWS];         // deg^{-1/2}
__device__ float g_proj[P * D];         // pos_emb @ w_att.T + b_att
__device__ float g_pew2[P];             // pos_emb[p] . w_weight[256:512]
__device__ float g_C0;                  // sum_p g_pew2[p]
__device__ float g_den [NROWS];         // softmax denom accumulator (exp-1 part)
__device__ float g_num [NROWS];         // context.w2 numerator accumulator
__device__ float g_out1[NROWS];         // sum over unique pos rows of dinv[i]*adj[i,j]
__device__ float g_vec [NROWS];         // reweighted vector before final matvec

// ---------------- K0: zero per-call accumulators ----------------
__global__ void k_zero() {
    int i = blockIdx.x * 256 + threadIdx.x;
    if (i < NROWS) { g_den[i] = 0.f; g_num[i] = 0.f; g_out1[i] = 0.f; }
    if (i == 0) g_C0 = 0.f;
}

// ---------------- K1: row sums + sparse extraction (the 256MB pass) ----------------
__global__ void k_rowsum(const float* __restrict__ adj) {
    int r = blockIdx.x;
    const float4* row = (const float4*)(adj + (size_t)r * NROWS);
    __shared__ int s_cnt;
    __shared__ float s_red[256];
    if (threadIdx.x == 0) s_cnt = 0;
    __syncthreads();

    float sum = 0.f;
    int* mycols = g_cols + (size_t)r * CAP;
    for (int c4 = threadIdx.x; c4 < NROWS / 4; c4 += 256) {
        float4 v = row[c4];
        sum += v.x + v.y + v.z + v.w;
        int base = c4 * 4;
        if (v.x != 0.f) { int s = atomicAdd(&s_cnt, 1); if (s < CAP) mycols[s] = base;     }
        if (v.y != 0.f) { int s = atomicAdd(&s_cnt, 1); if (s < CAP) mycols[s] = base + 1; }
        if (v.z != 0.f) { int s = atomicAdd(&s_cnt, 1); if (s < CAP) mycols[s] = base + 2; }
        if (v.w != 0.f) { int s = atomicAdd(&s_cnt, 1); if (s < CAP) mycols[s] = base + 3; }
    }
    s_red[threadIdx.x] = sum;
    __syncthreads();
    for (int o = 128; o > 0; o >>= 1) {
        if (threadIdx.x < o) s_red[threadIdx.x] += s_red[threadIdx.x + o];
        __syncthreads();
    }
    if (threadIdx.x == 0) {
        g_dinv[r] = rsqrtf(s_red[0]);       // deg >= 1 (self-loop)
        g_deg[r]  = min(s_cnt, CAP);
    }
}

// ---------------- K2: proj = pos_emb @ w_att.T + b_att ; pe_w2 ; C0 ----------------
__global__ void k_proj(const float* __restrict__ emb, const float* __restrict__ w_att,
                       const float* __restrict__ b_att, const float* __restrict__ w_weight,
                       const int* __restrict__ pos_idx) {
    int p = blockIdx.x;
    int d = threadIdx.x;
    __shared__ __align__(16) float s_e[D];
    __shared__ float s_red[D];
    int r = pos_idx[p];
    s_e[d] = emb[(size_t)r * D + d];
    __syncthreads();

    const float4* wrow = (const float4*)(w_att + (size_t)d * D);
    const float4* se4  = (const float4*)s_e;
    float acc = b_att[d];
    #pragma unroll 8
    for (int q = 0; q < D / 4; q++) {
        float4 w = wrow[q]; float4 e = se4[q];
        acc += w.x * e.x + w.y * e.y + w.z * e.z + w.w * e.w;
    }
    g_proj[p * D + d] = acc;

    // pe_w2[p] = pos_emb[p] . w_weight[D:2D]
    s_red[d] = s_e[d] * w_weight[D + d];
    __syncthreads();
    for (int o = 128; o > 0; o >>= 1) {
        if (d < o) s_red[d] += s_red[d + o];
        __syncthreads();
    }
    if (d == 0) { g_pew2[p] = s_red[0]; atomicAdd(&g_C0, s_red[0]); }
}

// ---------------- K3: attention scatter + out1 scatter over nnz(pos rows) ----------------
__global__ void k_att(const float* __restrict__ emb, const int* __restrict__ pos_idx) {
    int p = blockIdx.x;
    int r = pos_idx[p];
    __shared__ __align__(16) float s_proj[D];
    __shared__ int s_first;
    s_proj[threadIdx.x] = g_proj[p * D + threadIdx.x];
    if (threadIdx.x == 0) {
        // inputs is a one-hot SET: duplicate pos indices count once in out1
        s_first = (p == 0) || (pos_idx[p - 1] != r);
    }
    __syncthreads();

    float pw2 = g_pew2[p];
    float di  = g_dinv[r];
    int   deg = g_deg[r];
    int warp = threadIdx.x >> 5, lane = threadIdx.x & 31;
    const float4* pr4 = (const float4*)s_proj;

    for (int t = warp; t < deg; t += 8) {
        int j = g_cols[(size_t)r * CAP + t];
        const float4* ej = (const float4*)(emb + (size_t)j * D);
        float acc = 0.f;
        #pragma unroll
        for (int q = lane; q < D / 4; q += 32) {
            float4 e = ej[q]; float4 pp = pr4[q];
            acc += e.x * pp.x + e.y * pp.y + e.z * pp.z + e.w * pp.w;
        }
        #pragma unroll
        for (int o = 16; o > 0; o >>= 1) acc += __shfl_xor_sync(0xffffffff, acc, o);
        if (lane == 0) {
            float e = expf(acc) - 1.0f;   // exp(score) - exp(0)
            atomicAdd(&g_den[j], e);
            atomicAdd(&g_num[j], e * pw2);
            if (s_first) atomicAdd(&g_out1[j], di);
        }
    }
}

// ---------------- K4: mutual_w + reweight: vec[j] = dinv[j]*out1acc[j]*sigmoid(...) ----------------
__global__ void k_mutual(const float* __restrict__ emb, const float* __restrict__ w_weight) {
    int j = blockIdx.x * 8 + (threadIdx.x >> 5);
    int lane = threadIdx.x & 31;
    if (j >= NROWS) return;
    const float4* ej = (const float4*)(emb + (size_t)j * D);
    const float4* w1 = (const float4*)w_weight;   // first D entries
    float acc = 0.f;
    #pragma unroll
    for (int q = lane; q < D / 4; q += 32) {
        float4 e = ej[q]; float4 w = w1[q];
        acc += e.x * w.x + e.y * w.y + e.z * w.z + e.w * w.w;
    }
    #pragma unroll
    for (int o = 16; o > 0; o >>= 1) acc += __shfl_xor_sync(0xffffffff, acc, o);
    if (lane == 0) {
        float ctx = (g_C0 + g_num[j]) / (128.0f + g_den[j]);
        float mw  = 1.0f / (1.0f + expf(-(acc + ctx)));
        g_vec[j] = g_dinv[j] * g_out1[j] * mw;
    }
}

// ---------------- K5: out[j] = w_final * dinv[j] * sum_{i in nbr(j)} vec[i] ----------------
__global__ void k_final(float* __restrict__ out, const float* __restrict__ w_final) {
    int j = blockIdx.x * 8 + (threadIdx.x >> 5);
    int lane = threadIdx.x & 31;
    if (j >= NROWS) return;
    int deg = g_deg[j];
    const int* cols = g_cols + (size_t)j * CAP;
    float acc = 0.f;
    for (int t = lane; t < deg; t += 32) acc += g_vec[cols[t]];
    #pragma unroll
    for (int o = 16; o > 0; o >>= 1) acc += __shfl_xor_sync(0xffffffff, acc, o);
    if (lane == 0) out[j] = g_dinv[j] * acc * w_final[0];
}

// ---------------- launch ----------------
extern "C" void kernel_launch(void* const* d_in, const int* in_sizes, int n_in,
                              void* d_out, int out_size) {
    const float* adj      = (const float*)d_in[0];
    const float* emb      = (const float*)d_in[1];
    const float* w_att    = (const float*)d_in[2];
    const float* b_att    = (const float*)d_in[3];
    const float* w_weight = (const float*)d_in[4];
    const float* w_final  = (const float*)d_in[5];
    const int*   pos_idx  = (const int*)  d_in[6];
    float* out = (float*)d_out;

    k_zero  <<<(NROWS + 255) / 256 + 1, 256>>>();
    k_rowsum<<<NROWS, 256>>>(adj);
    k_proj  <<<P, D>>>(emb, w_att, b_att, w_weight, pos_idx);
    k_att   <<<P, D>>>(emb, pos_idx);
    k_mutual<<<NROWS / 8, 256>>>(emb, w_weight);
    k_final <<<NROWS / 8, 256>>>(out, w_final);
}

// round 2
// speedup vs baseline: 1.3787x; 1.3787x over previous
#include <cuda_runtime.h>
#include <cuda_bf16.h>
#include <math.h>

#define NROWS 8000
#define NV4   2000      // NROWS/4
#define D     256
#define P     128
#define CAP   192       // max nnz/row; binomial mean ~64, max ~105
#define FULL_IT 7       // 7*256 = 1792 unconditional float4 loads per thread-block
#define TAIL  208       // 2000 - 1792

// ---------------- device scratch ----------------
__device__ int   g_cols[NROWS * CAP];
__device__ int   g_deg [NROWS];
__device__ float g_dinv[NROWS];
__device__ float g_pew2[P];
__device__ float g_den [NROWS];
__device__ float g_num [NROWS];
__device__ float g_out1[NROWS];
__device__ float g_vec [NROWS];

// ---------------- K0: zero accumulators ----------------
__global__ void k_zero() {
    int i = blockIdx.x * 256 + threadIdx.x;
    if (i < NROWS) { g_den[i] = 0.f; g_num[i] = 0.f; g_out1[i] = 0.f; }
}

// ---------------- lean row scan: batched loads + OR-tree + rare hit path ----------
// adj values are exactly 0.0f or 1.0f, so nonzero test = integer bits != 0 and
// deg = hit count (no float sum needed).
__device__ __forceinline__ void scan_row(const uint4* __restrict__ row,
                                         int* cols, int* s_cnt) {
    int tid = threadIdx.x;
    uint4 v[FULL_IT];
    #pragma unroll
    for (int k = 0; k < FULL_IT; k++) v[k] = row[tid + 256 * k];
    uint4 t = make_uint4(0u, 0u, 0u, 0u);
    if (tid < TAIL) t = row[1792 + tid];

    unsigned orr = t.x | t.y | t.z | t.w;
    #pragma unroll
    for (int k = 0; k < FULL_IT; k++) orr |= v[k].x | v[k].y | v[k].z | v[k].w;

    if (orr) {  // rare: ~5-6% of threads
        #pragma unroll
        for (int k = 0; k < FULL_IT; k++) {
            int base = 4 * (tid + 256 * k);
            if (v[k].x) { int s = atomicAdd(s_cnt, 1); if (s < CAP) cols[s] = base;     }
            if (v[k].y) { int s = atomicAdd(s_cnt, 1); if (s < CAP) cols[s] = base + 1; }
            if (v[k].z) { int s = atomicAdd(s_cnt, 1); if (s < CAP) cols[s] = base + 2; }
            if (v[k].w) { int s = atomicAdd(s_cnt, 1); if (s < CAP) cols[s] = base + 3; }
        }
        int base = 4 * (1792 + tid);
        if (t.x) { int s = atomicAdd(s_cnt, 1); if (s < CAP) cols[s] = base;     }
        if (t.y) { int s = atomicAdd(s_cnt, 1); if (s < CAP) cols[s] = base + 1; }
        if (t.z) { int s = atomicAdd(s_cnt, 1); if (s < CAP) cols[s] = base + 2; }
        if (t.w) { int s = atomicAdd(s_cnt, 1); if (s < CAP) cols[s] = base + 3; }
    }
}

// ---------------- K1: fused big pass ----------------
// blocks [0, P)      : attention blocks (own row scan + proj + pair dots + scatter)
// blocks [P, P+8000) : row scan -> g_cols / g_deg / g_dinv
__global__ void k_fused(const float* __restrict__ adj,
                        const float* __restrict__ emb,
                        const float* __restrict__ w_att,
                        const float* __restrict__ b_att,
                        const float* __restrict__ w_weight,
                        const int*   __restrict__ pos_idx) {
    __shared__ int s_cnt;
    int tid = threadIdx.x;

    if (blockIdx.x >= P) {
        // -------- plain row: extract sparsity --------
        int r = blockIdx.x - P;
        if (tid == 0) s_cnt = 0;
        __syncthreads();
        scan_row((const uint4*)(adj + (size_t)r * NROWS), g_cols + (size_t)r * CAP, &s_cnt);
        __syncthreads();
        if (tid == 0) {
            int deg = min(s_cnt, CAP);
            g_deg[r]  = deg;
            g_dinv[r] = rsqrtf((float)s_cnt);   // deg >= 1 (self-loop)
        }
        return;
    }

    // -------- attention block for positive p --------
    __shared__ int   s_cols[CAP];
    __shared__ __align__(16) float s_emb[D];
    __shared__ __align__(16) float s_proj[D];
    __shared__ float s_red[8];

    int p = blockIdx.x;
    int r = pos_idx[p];
    if (tid == 0) s_cnt = 0;
    __syncthreads();
    scan_row((const uint4*)(adj + (size_t)r * NROWS), s_cols, &s_cnt);

    // load this row's embedding
    s_emb[tid] = emb[(size_t)r * D + tid];
    __syncthreads();

    int   deg    = min(s_cnt, CAP);
    float dinv_r = rsqrtf((float)s_cnt);
    bool  first  = (p == 0) || (pos_idx[p - 1] != r);  // one-hot SET semantics

    // proj[d] = dot(w_att[d,:], emb_r) + b_att[d]
    {
        const float4* wrow = (const float4*)(w_att + (size_t)tid * D);
        const float4* e4   = (const float4*)s_emb;
        float acc = b_att[tid];
        #pragma unroll 8
        for (int q = 0; q < D / 4; q++) {
            float4 w = wrow[q]; float4 e = e4[q];
            acc += w.x * e.x + w.y * e.y + w.z * e.z + w.w * e.w;
        }
        s_proj[tid] = acc;
    }

    // pew2[p] = dot(emb_r, w_weight[D:2D])
    int warp = tid >> 5, lane = tid & 31;
    {
        float v = s_emb[tid] * w_weight[D + tid];
        #pragma unroll
        for (int o = 16; o > 0; o >>= 1) v += __shfl_xor_sync(0xffffffff, v, o);
        if (lane == 0) s_red[warp] = v;
    }
    __syncthreads();
    float pw2 = s_red[0] + s_red[1] + s_red[2] + s_red[3]
              + s_red[4] + s_red[5] + s_red[6] + s_red[7];
    if (tid == 0) g_pew2[p] = pw2;

    // pair dots: warp per neighbor
    const float4* pr4 = (const float4*)s_proj;
    for (int t = warp; t < deg; t += 8) {
        int j = s_cols[t];
        const float4* ej = (const float4*)(emb + (size_t)j * D);
        float acc = 0.f;
        #pragma unroll
        for (int q = lane; q < D / 4; q += 32) {
            float4 e = ej[q]; float4 pp = pr4[q];
            acc += e.x * pp.x + e.y * pp.y + e.z * pp.z + e.w * pp.w;
        }
        #pragma unroll
        for (int o = 16; o > 0; o >>= 1) acc += __shfl_xor_sync(0xffffffff, acc, o);
        if (lane == 0) {
            float e = expm1f(acc);            // exp(score) - exp(0)
            atomicAdd(&g_den[j], e);
            atomicAdd(&g_num[j], e * pw2);
            if (first) atomicAdd(&g_out1[j], dinv_r);
        }
    }
}

// ---------------- K2: mutual weight + reweight ----------------
__global__ void k_mutual(const float* __restrict__ emb,
                         const float* __restrict__ w_weight) {
    __shared__ float s_c0p[4];
    __shared__ float s_c0;
    int tid = threadIdx.x, warp = tid >> 5, lane = tid & 31;

    // C0 = sum_p pew2[p] (computed per block; g_pew2 is 512B, L2-hot)
    if (tid < P) {
        float v = g_pew2[tid];
        #pragma unroll
        for (int o = 16; o > 0; o >>= 1) v += __shfl_xor_sync(0xffffffff, v, o);
        if (lane == 0) s_c0p[warp] = v;
    }
    __syncthreads();
    if (tid == 0) s_c0 = s_c0p[0] + s_c0p[1] + s_c0p[2] + s_c0p[3];
    __syncthreads();
    float C0 = s_c0;

    int j = blockIdx.x * 8 + warp;
    if (j >= NROWS) return;
    const float4* ej = (const float4*)(emb + (size_t)j * D);
    const float4* w1 = (const float4*)w_weight;
    float acc = 0.f;
    #pragma unroll
    for (int q = lane; q < D / 4; q += 32) {
        float4 e = ej[q]; float4 w = w1[q];
        acc += e.x * w.x + e.y * w.y + e.z * w.z + e.w * w.w;
    }
    #pragma unroll
    for (int o = 16; o > 0; o >>= 1) acc += __shfl_xor_sync(0xffffffff, acc, o);
    if (lane == 0) {
        float ctx = (C0 + g_num[j]) / ((float)P + g_den[j]);
        float mw  = 1.0f / (1.0f + expf(-(acc + ctx)));
        g_vec[j] = g_dinv[j] * g_out1[j] * mw;
    }
}

// ---------------- K3: out[j] = w_final * dinv[j] * sum_{i in nbr(j)} vec[i] ------
__global__ void k_final(float* __restrict__ out, const float* __restrict__ w_final) {
    int j = blockIdx.x * 8 + (threadIdx.x >> 5);
    int lane = threadIdx.x & 31;
    if (j >= NROWS) return;
    int deg = g_deg[j];
    const int* cols = g_cols + (size_t)j * CAP;
    float acc = 0.f;
    for (int t = lane; t < deg; t += 32) acc += g_vec[cols[t]];
    #pragma unroll
    for (int o = 16; o > 0; o >>= 1) acc += __shfl_xor_sync(0xffffffff, acc, o);
    if (lane == 0) out[j] = g_dinv[j] * acc * w_final[0];
}

// ---------------- launch ----------------
extern "C" void kernel_launch(void* const* d_in, const int* in_sizes, int n_in,
                              void* d_out, int out_size) {
    const float* adj      = (const float*)d_in[0];
    const float* emb      = (const float*)d_in[1];
    const float* w_att    = (const float*)d_in[2];
    const float* b_att    = (const float*)d_in[3];
    const float* w_weight = (const float*)d_in[4];
    const float* w_final  = (const float*)d_in[5];
    const int*   pos_idx  = (const int*)  d_in[6];
    float* out = (float*)d_out;

    k_zero  <<<(NROWS + 255) / 256, 256>>>();
    k_fused <<<NROWS + P, 256>>>(adj, emb, w_att, b_att, w_weight, pos_idx);
    k_mutual<<<NROWS / 8, 256>>>(emb, w_weight);
    k_final <<<NROWS / 8, 256>>>(out, w_final);
}